// round 12
// baseline (speedup 1.0000x reference)
#include <cuda_runtime.h>
#include <cuda_bf16.h>
#include <cstdint>

#define BATCH   32768
#define NSITES  64
#define NBULK   62
#define NPAIR   31
#define NSETS   (NPAIR * 4)            // 124 pass-sets
#define TPB     32
#define NCTA    (BATCH / 32)           // 1024 single-warp CTAs

// Fragment-linear B operands for fused site-pairs:
// set S = pair*4 + g,  g: 0=M0aM0b, 1=DaM0b, 2=M0aDb, 3=DaDb
// word index = (((S*2 + limb)*4 + j)*32 + lane)*4 + m   (limb 0=hi, 1=lo)
__device__ __align__(256) uint4 g_bfrags[(NSETS + 1) * 2 * 4 * 32];

// ---------------- helpers ----------------
__device__ __forceinline__ void mma16816(float* d, const uint32_t* a, uint32_t b0, uint32_t b1) {
    asm("mma.sync.aligned.m16n8k16.row.col.f32.bf16.bf16.f32 "
        "{%0,%1,%2,%3}, {%4,%5,%6,%7}, {%8,%9}, {%0,%1,%2,%3};"
        : "+f"(d[0]), "+f"(d[1]), "+f"(d[2]), "+f"(d[3])
        : "r"(a[0]), "r"(a[1]), "r"(a[2]), "r"(a[3]), "r"(b0), "r"(b1));
}
__device__ __forceinline__ void mma16816_z(float* d, const uint32_t* a, uint32_t b0, uint32_t b1,
                                           const float* z) {
    asm("mma.sync.aligned.m16n8k16.row.col.f32.bf16.bf16.f32 "
        "{%0,%1,%2,%3}, {%4,%5,%6,%7}, {%8,%9}, {%10,%11,%12,%13};"
        : "=f"(d[0]), "=f"(d[1]), "=f"(d[2]), "=f"(d[3])
        : "r"(a[0]), "r"(a[1]), "r"(a[2]), "r"(a[3]), "r"(b0), "r"(b1),
          "f"(z[0]), "f"(z[1]), "f"(z[2]), "f"(z[3]));
}
__device__ __forceinline__ uint32_t packbf(float lo, float hi) {
    uint32_t r;
    asm("cvt.rn.bf16x2.f32 %0, %1, %2;" : "=r"(r) : "f"(hi), "f"(lo));
    return r;
}
__device__ __forceinline__ uint32_t packbf_trunc(uint32_t u0, uint32_t u1) {
    uint32_t r;
    asm("prmt.b32 %0, %1, %2, 0x7632;" : "=r"(r) : "r"(u0), "r"(u1));
    return r;
}
__device__ __forceinline__ void split2(float x0, float x1, uint32_t& hp, uint32_t& lp) {
    uint32_t u0 = __float_as_uint(x0), u1 = __float_as_uint(x1);
    hp = packbf_trunc(u0, u1);
    float l0 = x0 - __uint_as_float(u0 & 0xFFFF0000u);
    float l1 = x1 - __uint_as_float(u1 & 0xFFFF0000u);
    lp = packbf(l0, l1);
}

// one 48-MMA pass, term-major
__device__ __forceinline__ void do_pass(float acc[2][4][4],
                                        const uint32_t ah[2][2][4],
                                        const uint32_t al[2][2][4],
                                        const uint4* b) {
    #pragma unroll
    for (int j = 0; j < 4; j++) { mma16816(acc[0][j], ah[0][0], b[j].x, b[j].y);
                                  mma16816(acc[1][j], ah[1][0], b[j].x, b[j].y); }
    #pragma unroll
    for (int j = 0; j < 4; j++) { mma16816(acc[0][j], ah[0][1], b[j].z, b[j].w);
                                  mma16816(acc[1][j], ah[1][1], b[j].z, b[j].w); }
    #pragma unroll
    for (int j = 0; j < 4; j++) { mma16816(acc[0][j], al[0][0], b[j].x, b[j].y);
                                  mma16816(acc[1][j], al[1][0], b[j].x, b[j].y); }
    #pragma unroll
    for (int j = 0; j < 4; j++) { mma16816(acc[0][j], al[0][1], b[j].z, b[j].w);
                                  mma16816(acc[1][j], al[1][1], b[j].z, b[j].w); }
    #pragma unroll
    for (int j = 0; j < 4; j++) { mma16816(acc[0][j], ah[0][0], b[4+j].x, b[4+j].y);
                                  mma16816(acc[1][j], ah[1][0], b[4+j].x, b[4+j].y); }
    #pragma unroll
    for (int j = 0; j < 4; j++) { mma16816(acc[0][j], ah[0][1], b[4+j].z, b[4+j].w);
                                  mma16816(acc[1][j], ah[1][1], b[4+j].z, b[4+j].w); }
}
// first pass: initializes acc from zero regs
__device__ __forceinline__ void do_pass_first(float acc[2][4][4],
                                              const uint32_t ah[2][2][4],
                                              const uint32_t al[2][2][4],
                                              const uint4* b, const float* z4) {
    #pragma unroll
    for (int j = 0; j < 4; j++) { mma16816_z(acc[0][j], ah[0][0], b[j].x, b[j].y, z4);
                                  mma16816_z(acc[1][j], ah[1][0], b[j].x, b[j].y, z4); }
    #pragma unroll
    for (int j = 0; j < 4; j++) { mma16816(acc[0][j], ah[0][1], b[j].z, b[j].w);
                                  mma16816(acc[1][j], ah[1][1], b[j].z, b[j].w); }
    #pragma unroll
    for (int j = 0; j < 4; j++) { mma16816(acc[0][j], al[0][0], b[j].x, b[j].y);
                                  mma16816(acc[1][j], al[1][0], b[j].x, b[j].y); }
    #pragma unroll
    for (int j = 0; j < 4; j++) { mma16816(acc[0][j], al[0][1], b[j].z, b[j].w);
                                  mma16816(acc[1][j], al[1][1], b[j].z, b[j].w); }
    #pragma unroll
    for (int j = 0; j < 4; j++) { mma16816(acc[0][j], ah[0][0], b[4+j].x, b[4+j].y);
                                  mma16816(acc[1][j], ah[1][0], b[4+j].x, b[4+j].y); }
    #pragma unroll
    for (int j = 0; j < 4; j++) { mma16816(acc[0][j], ah[0][1], b[4+j].z, b[4+j].w);
                                  mma16816(acc[1][j], ah[1][1], b[4+j].z, b[4+j].w); }
}

// build a masked copy of the A fragments (per-row c bits)
__device__ __forceinline__ void mask_copy(uint32_t dh[2][2][4], uint32_t dl[2][2][4],
                                          const uint32_t sh[2][2][4], const uint32_t sl[2][2][4],
                                          uint32_t c0, uint32_t c1, uint32_t c2, uint32_t c3) {
    #pragma unroll
    for (int kt = 0; kt < 2; kt++)
        #pragma unroll
        for (int h = 0; h < 2; h++) {
            dh[0][kt][2*h]   = c0 ? sh[0][kt][2*h]   : 0u;
            dl[0][kt][2*h]   = c0 ? sl[0][kt][2*h]   : 0u;
            dh[0][kt][2*h+1] = c1 ? sh[0][kt][2*h+1] : 0u;
            dl[0][kt][2*h+1] = c1 ? sl[0][kt][2*h+1] : 0u;
            dh[1][kt][2*h]   = c2 ? sh[1][kt][2*h]   : 0u;
            dl[1][kt][2*h]   = c2 ? sl[1][kt][2*h]   : 0u;
            dh[1][kt][2*h+1] = c3 ? sh[1][kt][2*h+1] : 0u;
            dl[1][kt][2*h+1] = c3 ? sl[1][kt][2*h+1] : 0u;
        }
}

// ---------------- prep: build fused-pair product matrices + fragments ----------------
__global__ void prep_kernel(const float* __restrict__ bulk) {
    const int p = blockIdx.x;                        // pair index
    const float* ba = bulk + (size_t)(2 * p)     * 2048;   // site a: [d][c][e]
    const float* bb = bulk + (size_t)(2 * p + 1) * 2048;   // site b
    __shared__ float G[4][1024];                     // G[g][d*32+e]

    // phase 1: G_g = Ma' (32x32) * Mb' (32x32),  Ma' in {M0a, Da}, Mb' in {M0b, Db}
    for (int idx = threadIdx.x; idx < 4096; idx += blockDim.x) {
        int g = idx >> 10;
        int d = (idx >> 5) & 31;
        int e = idx & 31;
        int selA = g & 1, selB = g >> 1;
        float s = 0.0f;
        #pragma unroll 8
        for (int m = 0; m < 32; m++) {
            float va = ba[(d * 2 + 0) * 32 + m];
            if (selA) va = ba[(d * 2 + 1) * 32 + m] - va;
            float vb = bb[(m * 2 + 0) * 32 + e];
            if (selB) vb = bb[(m * 2 + 1) * 32 + e] - vb;
            s += va * vb;
        }
        G[g][d * 32 + e] = s;
    }
    __syncthreads();

    // phase 2: emit fragment-linear bf16 hi/lo words
    // word for (g, limb, j, lane, m): pair (G[k][n], G[k+1][n]), n = 8j+(lane>>2), k = 8m+2(lane&3)
    for (int idx = threadIdx.x; idx < 4096; idx += blockDim.x) {
        int m    = idx & 3;
        int lane = (idx >> 2) & 31;
        int j    = (idx >> 7) & 3;
        int limb = (idx >> 9) & 1;
        int g    = idx >> 10;
        int n = 8 * j + (lane >> 2);
        int k = 8 * m + 2 * (lane & 3);
        float x0 = G[g][k * 32 + n];
        float x1 = G[g][(k + 1) * 32 + n];
        float v0, v1;
        if (limb) {
            __nv_bfloat16 h0 = __float2bfloat16(x0);
            __nv_bfloat16 h1 = __float2bfloat16(x1);
            v0 = x0 - __bfloat162float(h0);
            v1 = x1 - __bfloat162float(h1);
        } else { v0 = x0; v1 = x1; }
        int S = p * 4 + g;
        ((uint32_t*)g_bfrags)[(((S * 2 + limb) * 4 + j) * 32 + lane) * 4 + m] = packbf(v0, v1);
    }
}

// ---------------- main kernel ----------------
// ONE warp per CTA (32 samples), grid 1024 -> max 7 warps/SM (balanced).
__global__ void __launch_bounds__(TPB)
mps_mma_kernel(const int*   __restrict__ conf,
               const float* __restrict__ left,
               const float* __restrict__ right,
               float*       __restrict__ out)
{
    __shared__ float lt_s[64];
    __shared__ float rt_s[64];
    __shared__ unsigned long long masks_s[32];

    const int lane = threadIdx.x;
    const int rowq = lane >> 2;
    const int q    = lane & 3;

    lt_s[lane] = left[lane];   lt_s[lane + 32] = left[lane + 32];
    rt_s[lane] = right[lane];  rt_s[lane + 32] = right[lane + 32];

    {
        unsigned long long mask = 0;
        const int4* cp4 = (const int4*)(conf + (size_t)(blockIdx.x * 32 + lane) * NSITES);
        #pragma unroll
        for (int i = 0; i < NSITES / 4; i++) {
            int4 v = cp4[i];
            mask |= ((unsigned long long)(v.x & 1) << (4 * i))
                  | ((unsigned long long)(v.y & 1) << (4 * i + 1))
                  | ((unsigned long long)(v.z & 1) << (4 * i + 2))
                  | ((unsigned long long)(v.w & 1) << (4 * i + 3));
        }
        masks_s[lane] = mask;
    }
    __syncwarp();

    unsigned long long mr[4];
    #pragma unroll
    for (int k = 0; k < 4; k++) mr[k] = masks_s[rowq + 8 * k];

    // ---- initial env = left[c0] as bf16 hi/lo A fragments ----
    uint32_t ah[2][2][4], al[2][2][4];   // [mtile][kt][reg]
    #pragma unroll
    for (int i = 0; i < 2; i++) {
        const int cA = (int)(mr[2 * i] & 1ull);
        const int cB = (int)(mr[2 * i + 1] & 1ull);
        #pragma unroll
        for (int kt = 0; kt < 2; kt++)
            #pragma unroll
            for (int h = 0; h < 2; h++) {
                int k0 = 16 * kt + 8 * h + 2 * q;
                uint32_t hA, lA, hB, lB;
                split2(lt_s[cA * 32 + k0], lt_s[cA * 32 + k0 + 1], hA, lA);
                split2(lt_s[cB * 32 + k0], lt_s[cB * 32 + k0 + 1], hB, lB);
                ah[i][kt][2 * h]     = hA;  ah[i][kt][2 * h + 1] = hB;
                al[i][kt][2 * h]     = lA;  al[i][kt][2 * h + 1] = lB;
            }
    }

    const uint4* fb = g_bfrags + lane;

    // prologue: load set 0 (pair 0, g=0) into buffer 0
    uint4 bb0[8], bb1[8];
    #pragma unroll
    for (int j = 0; j < 4; j++) {
        bb0[j]     = __ldg(fb + ((0 * 2 + 0) * 4 + j) * 32);
        bb0[4 + j] = __ldg(fb + ((0 * 2 + 1) * 4 + j) * 32);
    }

    const float z4[4] = {0.0f, 0.0f, 0.0f, 0.0f};
    float acc[2][4][4];
    uint32_t th[2][2][4], tl[2][2][4];   // masked A copies

    for (int p = 0; p < NPAIR; p++) {
        const uint32_t c1r[4] = {
            (uint32_t)((mr[0] >> (2 * p + 1)) & 1ull), (uint32_t)((mr[1] >> (2 * p + 1)) & 1ull),
            (uint32_t)((mr[2] >> (2 * p + 1)) & 1ull), (uint32_t)((mr[3] >> (2 * p + 1)) & 1ull) };
        const uint32_t c2r[4] = {
            (uint32_t)((mr[0] >> (2 * p + 2)) & 1ull), (uint32_t)((mr[1] >> (2 * p + 2)) & 1ull),
            (uint32_t)((mr[2] >> (2 * p + 2)) & 1ull), (uint32_t)((mr[3] >> (2 * p + 2)) & 1ull) };

        #pragma unroll
        for (int g = 0; g < 4; g++) {
            const int S = p * 4 + g;
            uint4* cur = (g & 1) ? bb1 : bb0;
            uint4* nxt = (g & 1) ? bb0 : bb1;
            // prefetch set S+1 into the other buffer
            if (S + 1 < NSETS) {
                #pragma unroll
                for (int j = 0; j < 4; j++) {
                    nxt[j]     = __ldg(fb + (((S + 1) * 2 + 0) * 4 + j) * 32);
                    nxt[4 + j] = __ldg(fb + (((S + 1) * 2 + 1) * 4 + j) * 32);
                }
            }
            if (g == 0) {
                do_pass_first(acc, ah, al, cur, z4);                 // E * M0a*M0b
            } else if (g == 1) {
                mask_copy(th, tl, ah, al, c1r[0], c1r[1], c1r[2], c1r[3]);
                do_pass(acc, th, tl, cur);                           // c1*E * Da*M0b
            } else if (g == 2) {
                mask_copy(th, tl, ah, al, c2r[0], c2r[1], c2r[2], c2r[3]);
                do_pass(acc, th, tl, cur);                           // c2*E * M0a*Db
            } else {
                // mask the c2 copy again by c1 -> c1*c2*E
                #pragma unroll
                for (int kt = 0; kt < 2; kt++)
                    #pragma unroll
                    for (int h = 0; h < 2; h++) {
                        th[0][kt][2*h]   = c1r[0] ? th[0][kt][2*h]   : 0u;
                        tl[0][kt][2*h]   = c1r[0] ? tl[0][kt][2*h]   : 0u;
                        th[0][kt][2*h+1] = c1r[1] ? th[0][kt][2*h+1] : 0u;
                        tl[0][kt][2*h+1] = c1r[1] ? tl[0][kt][2*h+1] : 0u;
                        th[1][kt][2*h]   = c1r[2] ? th[1][kt][2*h]   : 0u;
                        tl[1][kt][2*h]   = c1r[2] ? tl[1][kt][2*h]   : 0u;
                        th[1][kt][2*h+1] = c1r[3] ? th[1][kt][2*h+1] : 0u;
                        tl[1][kt][2*h+1] = c1r[3] ? tl[1][kt][2*h+1] : 0u;
                    }
                do_pass(acc, th, tl, cur);                           // c1c2*E * Da*Db
            }
        }

        // ---- split pair result (acc) -> next A fragments (D-layout == A-layout) ----
        if (p + 1 < NPAIR) {
            #pragma unroll
            for (int i = 0; i < 2; i++)
                #pragma unroll
                for (int kt = 0; kt < 2; kt++)
                    #pragma unroll
                    for (int h = 0; h < 2; h++) {
                        uint32_t hA, lA, hB, lB;
                        split2(acc[i][2 * kt + h][0], acc[i][2 * kt + h][1], hA, lA);
                        split2(acc[i][2 * kt + h][2], acc[i][2 * kt + h][3], hB, lB);
                        ah[i][kt][2 * h]     = hA;  ah[i][kt][2 * h + 1] = hB;
                        al[i][kt][2 * h]     = lA;  al[i][kt][2 * h + 1] = lB;
                    }
        }
    }

    // ---- final dot with right[:, c63]; reduce across the 4 lanes of each row group ----
    float pr[4];
    #pragma unroll
    for (int i = 0; i < 2; i++) {
        const int cA = (int)(mr[2 * i]     >> 63);
        const int cB = (int)(mr[2 * i + 1] >> 63);
        float pa = 0.0f, pb = 0.0f;
        #pragma unroll
        for (int j = 0; j < 4; j++) {
            int n0 = 8 * j + 2 * q;
            pa += acc[i][j][0] * rt_s[n0 * 2 + cA] + acc[i][j][1] * rt_s[(n0 + 1) * 2 + cA];
            pb += acc[i][j][2] * rt_s[n0 * 2 + cB] + acc[i][j][3] * rt_s[(n0 + 1) * 2 + cB];
        }
        pr[2 * i]     = pa;
        pr[2 * i + 1] = pb;
    }
    #pragma unroll
    for (int k = 0; k < 4; k++) {
        pr[k] += __shfl_xor_sync(0xFFFFFFFF, pr[k], 1);
        pr[k] += __shfl_xor_sync(0xFFFFFFFF, pr[k], 2);
    }
    if (q == 0) {
        int base = blockIdx.x * 32 + rowq;
        #pragma unroll
        for (int k = 0; k < 4; k++) out[base + 8 * k] = pr[k];
    }
}

extern "C" void kernel_launch(void* const* d_in, const int* in_sizes, int n_in,
                              void* d_out, int out_size) {
    const int*   conf  = (const int*)d_in[0];
    const float* left  = (const float*)d_in[1];
    const float* bulk  = (const float*)d_in[2];
    const float* right = (const float*)d_in[3];
    float*       out   = (float*)d_out;

    prep_kernel<<<NPAIR, 256>>>(bulk);
    mps_mma_kernel<<<NCTA, TPB>>>(conf, left, right, out);
}

// round 13
// speedup vs baseline: 1.1950x; 1.1950x over previous
#include <cuda_runtime.h>
#include <cuda_bf16.h>
#include <cstdint>

#define BATCH   32768
#define NSITES  64
#define NBULK   62
#define NPAIR   31
#define NSETS   (NPAIR * 4)            // 124 pass-sets
#define TPB     32
#define NCTA    (BATCH / 32)           // 1024 single-warp CTAs

// Fragment-linear B operands for fused site-pairs:
// set S = pair*4 + g,  g: 0=M0aM0b, 1=DaM0b, 2=M0aDb, 3=DaDb
// word index = (((S*2 + limb)*4 + j)*32 + lane)*4 + m   (limb 0=hi, 1=lo)
__device__ __align__(256) uint4 g_bfrags[(NSETS + 1) * 2 * 4 * 32];

// ---------------- helpers ----------------
__device__ __forceinline__ void mma16816(float* d, const uint32_t* a, uint32_t b0, uint32_t b1) {
    asm("mma.sync.aligned.m16n8k16.row.col.f32.bf16.bf16.f32 "
        "{%0,%1,%2,%3}, {%4,%5,%6,%7}, {%8,%9}, {%0,%1,%2,%3};"
        : "+f"(d[0]), "+f"(d[1]), "+f"(d[2]), "+f"(d[3])
        : "r"(a[0]), "r"(a[1]), "r"(a[2]), "r"(a[3]), "r"(b0), "r"(b1));
}
__device__ __forceinline__ void mma16816_z(float* d, const uint32_t* a, uint32_t b0, uint32_t b1,
                                           const float* z) {
    asm("mma.sync.aligned.m16n8k16.row.col.f32.bf16.bf16.f32 "
        "{%0,%1,%2,%3}, {%4,%5,%6,%7}, {%8,%9}, {%10,%11,%12,%13};"
        : "=f"(d[0]), "=f"(d[1]), "=f"(d[2]), "=f"(d[3])
        : "r"(a[0]), "r"(a[1]), "r"(a[2]), "r"(a[3]), "r"(b0), "r"(b1),
          "f"(z[0]), "f"(z[1]), "f"(z[2]), "f"(z[3]));
}
__device__ __forceinline__ uint32_t packbf(float lo, float hi) {
    uint32_t r;
    asm("cvt.rn.bf16x2.f32 %0, %1, %2;" : "=r"(r) : "f"(hi), "f"(lo));
    return r;
}
__device__ __forceinline__ uint32_t packbf_trunc(uint32_t u0, uint32_t u1) {
    uint32_t r;
    asm("prmt.b32 %0, %1, %2, 0x7632;" : "=r"(r) : "r"(u0), "r"(u1));
    return r;
}
__device__ __forceinline__ void split2(float x0, float x1, uint32_t& hp, uint32_t& lp) {
    uint32_t u0 = __float_as_uint(x0), u1 = __float_as_uint(x1);
    hp = packbf_trunc(u0, u1);
    float l0 = x0 - __uint_as_float(u0 & 0xFFFF0000u);
    float l1 = x1 - __uint_as_float(u1 & 0xFFFF0000u);
    lp = packbf(l0, l1);
}

// one 48-MMA pass, term-major
__device__ __forceinline__ void do_pass(float acc[2][4][4],
                                        const uint32_t ah[2][2][4],
                                        const uint32_t al[2][2][4],
                                        const uint4* b) {
    #pragma unroll
    for (int j = 0; j < 4; j++) { mma16816(acc[0][j], ah[0][0], b[j].x, b[j].y);
                                  mma16816(acc[1][j], ah[1][0], b[j].x, b[j].y); }
    #pragma unroll
    for (int j = 0; j < 4; j++) { mma16816(acc[0][j], ah[0][1], b[j].z, b[j].w);
                                  mma16816(acc[1][j], ah[1][1], b[j].z, b[j].w); }
    #pragma unroll
    for (int j = 0; j < 4; j++) { mma16816(acc[0][j], al[0][0], b[j].x, b[j].y);
                                  mma16816(acc[1][j], al[1][0], b[j].x, b[j].y); }
    #pragma unroll
    for (int j = 0; j < 4; j++) { mma16816(acc[0][j], al[0][1], b[j].z, b[j].w);
                                  mma16816(acc[1][j], al[1][1], b[j].z, b[j].w); }
    #pragma unroll
    for (int j = 0; j < 4; j++) { mma16816(acc[0][j], ah[0][0], b[4+j].x, b[4+j].y);
                                  mma16816(acc[1][j], ah[1][0], b[4+j].x, b[4+j].y); }
    #pragma unroll
    for (int j = 0; j < 4; j++) { mma16816(acc[0][j], ah[0][1], b[4+j].z, b[4+j].w);
                                  mma16816(acc[1][j], ah[1][1], b[4+j].z, b[4+j].w); }
}
// first pass: initializes acc from zero regs
__device__ __forceinline__ void do_pass_first(float acc[2][4][4],
                                              const uint32_t ah[2][2][4],
                                              const uint32_t al[2][2][4],
                                              const uint4* b, const float* z4) {
    #pragma unroll
    for (int j = 0; j < 4; j++) { mma16816_z(acc[0][j], ah[0][0], b[j].x, b[j].y, z4);
                                  mma16816_z(acc[1][j], ah[1][0], b[j].x, b[j].y, z4); }
    #pragma unroll
    for (int j = 0; j < 4; j++) { mma16816(acc[0][j], ah[0][1], b[j].z, b[j].w);
                                  mma16816(acc[1][j], ah[1][1], b[j].z, b[j].w); }
    #pragma unroll
    for (int j = 0; j < 4; j++) { mma16816(acc[0][j], al[0][0], b[j].x, b[j].y);
                                  mma16816(acc[1][j], al[1][0], b[j].x, b[j].y); }
    #pragma unroll
    for (int j = 0; j < 4; j++) { mma16816(acc[0][j], al[0][1], b[j].z, b[j].w);
                                  mma16816(acc[1][j], al[1][1], b[j].z, b[j].w); }
    #pragma unroll
    for (int j = 0; j < 4; j++) { mma16816(acc[0][j], ah[0][0], b[4+j].x, b[4+j].y);
                                  mma16816(acc[1][j], ah[1][0], b[4+j].x, b[4+j].y); }
    #pragma unroll
    for (int j = 0; j < 4; j++) { mma16816(acc[0][j], ah[0][1], b[4+j].z, b[4+j].w);
                                  mma16816(acc[1][j], ah[1][1], b[4+j].z, b[4+j].w); }
}

// build a masked copy of the A fragments (per-row c bits)
__device__ __forceinline__ void mask_copy(uint32_t dh[2][2][4], uint32_t dl[2][2][4],
                                          const uint32_t sh[2][2][4], const uint32_t sl[2][2][4],
                                          uint32_t c0, uint32_t c1, uint32_t c2, uint32_t c3) {
    #pragma unroll
    for (int kt = 0; kt < 2; kt++)
        #pragma unroll
        for (int h = 0; h < 2; h++) {
            dh[0][kt][2*h]   = c0 ? sh[0][kt][2*h]   : 0u;
            dl[0][kt][2*h]   = c0 ? sl[0][kt][2*h]   : 0u;
            dh[0][kt][2*h+1] = c1 ? sh[0][kt][2*h+1] : 0u;
            dl[0][kt][2*h+1] = c1 ? sl[0][kt][2*h+1] : 0u;
            dh[1][kt][2*h]   = c2 ? sh[1][kt][2*h]   : 0u;
            dl[1][kt][2*h]   = c2 ? sl[1][kt][2*h]   : 0u;
            dh[1][kt][2*h+1] = c3 ? sh[1][kt][2*h+1] : 0u;
            dl[1][kt][2*h+1] = c3 ? sl[1][kt][2*h+1] : 0u;
        }
}

// ---------------- prep: one block per (pair,g) pass-set; SMEM-staged tiny GEMM ----------------
__global__ void prep_kernel(const float* __restrict__ bulk) {
    const int S = blockIdx.x;                        // 0..123
    const int p = S >> 2;
    const int g = S & 3;
    const int selA = g & 1, selB = g >> 1;
    const float* ba = bulk + (size_t)(2 * p)     * 2048;   // site a: [d][c][e]
    const float* bb = bulk + (size_t)(2 * p + 1) * 2048;   // site b

    __shared__ float Ma[1024];   // Ma[d*32+m]  (selected: M0a or Da)
    __shared__ float Mb[1024];   // Mb[m*32+e]  (selected: M0b or Db)
    __shared__ float G[1024];    // G[k*32+n] = sum_m Ma[k][m]*Mb[m][n]

    // stage operands (coalesced: consecutive tid -> consecutive inner index)
    for (int i = threadIdx.x; i < 1024; i += blockDim.x) {
        int r = i >> 5, c = i & 31;
        float va = ba[(r * 2 + 0) * 32 + c];
        if (selA) va = ba[(r * 2 + 1) * 32 + c] - va;
        Ma[i] = va;
        float vb = bb[(r * 2 + 0) * 32 + c];
        if (selB) vb = bb[(r * 2 + 1) * 32 + c] - vb;
        Mb[i] = vb;
    }
    __syncthreads();

    // G = Ma * Mb  (each thread: 4 output elements)
    for (int i = threadIdx.x; i < 1024; i += blockDim.x) {
        int d = i >> 5, e = i & 31;
        float s = 0.0f;
        #pragma unroll
        for (int m = 0; m < 32; m++) s += Ma[d * 32 + m] * Mb[m * 32 + e];
        G[i] = s;
    }
    __syncthreads();

    // emit fragment-linear bf16 hi/lo words (2048 words)
    for (int idx = threadIdx.x; idx < 2048; idx += blockDim.x) {
        int m    = idx & 3;
        int lane = (idx >> 2) & 31;
        int j    = (idx >> 7) & 3;
        int limb = (idx >> 9) & 1;
        int n = 8 * j + (lane >> 2);
        int k = 8 * m + 2 * (lane & 3);
        float x0 = G[k * 32 + n];
        float x1 = G[(k + 1) * 32 + n];
        float v0, v1;
        if (limb) {
            __nv_bfloat16 h0 = __float2bfloat16(x0);
            __nv_bfloat16 h1 = __float2bfloat16(x1);
            v0 = x0 - __bfloat162float(h0);
            v1 = x1 - __bfloat162float(h1);
        } else { v0 = x0; v1 = x1; }
        ((uint32_t*)g_bfrags)[(((S * 2 + limb) * 4 + j) * 32 + lane) * 4 + m] = packbf(v0, v1);
    }
}

// ---------------- main kernel (identical to R12) ----------------
__global__ void __launch_bounds__(TPB)
mps_mma_kernel(const int*   __restrict__ conf,
               const float* __restrict__ left,
               const float* __restrict__ right,
               float*       __restrict__ out)
{
    __shared__ float lt_s[64];
    __shared__ float rt_s[64];
    __shared__ unsigned long long masks_s[32];

    const int lane = threadIdx.x;
    const int rowq = lane >> 2;
    const int q    = lane & 3;

    lt_s[lane] = left[lane];   lt_s[lane + 32] = left[lane + 32];
    rt_s[lane] = right[lane];  rt_s[lane + 32] = right[lane + 32];

    {
        unsigned long long mask = 0;
        const int4* cp4 = (const int4*)(conf + (size_t)(blockIdx.x * 32 + lane) * NSITES);
        #pragma unroll
        for (int i = 0; i < NSITES / 4; i++) {
            int4 v = cp4[i];
            mask |= ((unsigned long long)(v.x & 1) << (4 * i))
                  | ((unsigned long long)(v.y & 1) << (4 * i + 1))
                  | ((unsigned long long)(v.z & 1) << (4 * i + 2))
                  | ((unsigned long long)(v.w & 1) << (4 * i + 3));
        }
        masks_s[lane] = mask;
    }
    __syncwarp();

    unsigned long long mr[4];
    #pragma unroll
    for (int k = 0; k < 4; k++) mr[k] = masks_s[rowq + 8 * k];

    // ---- initial env = left[c0] as bf16 hi/lo A fragments ----
    uint32_t ah[2][2][4], al[2][2][4];   // [mtile][kt][reg]
    #pragma unroll
    for (int i = 0; i < 2; i++) {
        const int cA = (int)(mr[2 * i] & 1ull);
        const int cB = (int)(mr[2 * i + 1] & 1ull);
        #pragma unroll
        for (int kt = 0; kt < 2; kt++)
            #pragma unroll
            for (int h = 0; h < 2; h++) {
                int k0 = 16 * kt + 8 * h + 2 * q;
                uint32_t hA, lA, hB, lB;
                split2(lt_s[cA * 32 + k0], lt_s[cA * 32 + k0 + 1], hA, lA);
                split2(lt_s[cB * 32 + k0], lt_s[cB * 32 + k0 + 1], hB, lB);
                ah[i][kt][2 * h]     = hA;  ah[i][kt][2 * h + 1] = hB;
                al[i][kt][2 * h]     = lA;  al[i][kt][2 * h + 1] = lB;
            }
    }

    const uint4* fb = g_bfrags + lane;

    // prologue: load set 0 (pair 0, g=0) into buffer 0
    uint4 bb0[8], bb1[8];
    #pragma unroll
    for (int j = 0; j < 4; j++) {
        bb0[j]     = __ldg(fb + ((0 * 2 + 0) * 4 + j) * 32);
        bb0[4 + j] = __ldg(fb + ((0 * 2 + 1) * 4 + j) * 32);
    }

    const float z4[4] = {0.0f, 0.0f, 0.0f, 0.0f};
    float acc[2][4][4];
    uint32_t th[2][2][4], tl[2][2][4];   // masked A copies

    for (int p = 0; p < NPAIR; p++) {
        const uint32_t c1r[4] = {
            (uint32_t)((mr[0] >> (2 * p + 1)) & 1ull), (uint32_t)((mr[1] >> (2 * p + 1)) & 1ull),
            (uint32_t)((mr[2] >> (2 * p + 1)) & 1ull), (uint32_t)((mr[3] >> (2 * p + 1)) & 1ull) };
        const uint32_t c2r[4] = {
            (uint32_t)((mr[0] >> (2 * p + 2)) & 1ull), (uint32_t)((mr[1] >> (2 * p + 2)) & 1ull),
            (uint32_t)((mr[2] >> (2 * p + 2)) & 1ull), (uint32_t)((mr[3] >> (2 * p + 2)) & 1ull) };

        #pragma unroll
        for (int g = 0; g < 4; g++) {
            const int S = p * 4 + g;
            uint4* cur = (g & 1) ? bb1 : bb0;
            uint4* nxt = (g & 1) ? bb0 : bb1;
            // prefetch set S+1 into the other buffer
            if (S + 1 < NSETS) {
                #pragma unroll
                for (int j = 0; j < 4; j++) {
                    nxt[j]     = __ldg(fb + (((S + 1) * 2 + 0) * 4 + j) * 32);
                    nxt[4 + j] = __ldg(fb + (((S + 1) * 2 + 1) * 4 + j) * 32);
                }
            }
            if (g == 0) {
                do_pass_first(acc, ah, al, cur, z4);                 // E * M0a*M0b
            } else if (g == 1) {
                mask_copy(th, tl, ah, al, c1r[0], c1r[1], c1r[2], c1r[3]);
                do_pass(acc, th, tl, cur);                           // c1*E * Da*M0b
            } else if (g == 2) {
                mask_copy(th, tl, ah, al, c2r[0], c2r[1], c2r[2], c2r[3]);
                do_pass(acc, th, tl, cur);                           // c2*E * M0a*Db
            } else {
                // mask the c2 copy again by c1 -> c1*c2*E
                #pragma unroll
                for (int kt = 0; kt < 2; kt++)
                    #pragma unroll
                    for (int h = 0; h < 2; h++) {
                        th[0][kt][2*h]   = c1r[0] ? th[0][kt][2*h]   : 0u;
                        tl[0][kt][2*h]   = c1r[0] ? tl[0][kt][2*h]   : 0u;
                        th[0][kt][2*h+1] = c1r[1] ? th[0][kt][2*h+1] : 0u;
                        tl[0][kt][2*h+1] = c1r[1] ? tl[0][kt][2*h+1] : 0u;
                        th[1][kt][2*h]   = c1r[2] ? th[1][kt][2*h]   : 0u;
                        tl[1][kt][2*h]   = c1r[2] ? tl[1][kt][2*h]   : 0u;
                        th[1][kt][2*h+1] = c1r[3] ? th[1][kt][2*h+1] : 0u;
                        tl[1][kt][2*h+1] = c1r[3] ? tl[1][kt][2*h+1] : 0u;
                    }
                do_pass(acc, th, tl, cur);                           // c1c2*E * Da*Db
            }
        }

        // ---- split pair result (acc) -> next A fragments (D-layout == A-layout) ----
        if (p + 1 < NPAIR) {
            #pragma unroll
            for (int i = 0; i < 2; i++)
                #pragma unroll
                for (int kt = 0; kt < 2; kt++)
                    #pragma unroll
                    for (int h = 0; h < 2; h++) {
                        uint32_t hA, lA, hB, lB;
                        split2(acc[i][2 * kt + h][0], acc[i][2 * kt + h][1], hA, lA);
                        split2(acc[i][2 * kt + h][2], acc[i][2 * kt + h][3], hB, lB);
                        ah[i][kt][2 * h]     = hA;  ah[i][kt][2 * h + 1] = hB;
                        al[i][kt][2 * h]     = lA;  al[i][kt][2 * h + 1] = lB;
                    }
        }
    }

    // ---- final dot with right[:, c63]; reduce across the 4 lanes of each row group ----
    float pr[4];
    #pragma unroll
    for (int i = 0; i < 2; i++) {
        const int cA = (int)(mr[2 * i]     >> 63);
        const int cB = (int)(mr[2 * i + 1] >> 63);
        float pa = 0.0f, pb = 0.0f;
        #pragma unroll
        for (int j = 0; j < 4; j++) {
            int n0 = 8 * j + 2 * q;
            pa += acc[i][j][0] * rt_s[n0 * 2 + cA] + acc[i][j][1] * rt_s[(n0 + 1) * 2 + cA];
            pb += acc[i][j][2] * rt_s[n0 * 2 + cB] + acc[i][j][3] * rt_s[(n0 + 1) * 2 + cB];
        }
        pr[2 * i]     = pa;
        pr[2 * i + 1] = pb;
    }
    #pragma unroll
    for (int k = 0; k < 4; k++) {
        pr[k] += __shfl_xor_sync(0xFFFFFFFF, pr[k], 1);
        pr[k] += __shfl_xor_sync(0xFFFFFFFF, pr[k], 2);
    }
    if (q == 0) {
        int base = blockIdx.x * 32 + rowq;
        #pragma unroll
        for (int k = 0; k < 4; k++) out[base + 8 * k] = pr[k];
    }
}

extern "C" void kernel_launch(void* const* d_in, const int* in_sizes, int n_in,
                              void* d_out, int out_size) {
    const int*   conf  = (const int*)d_in[0];
    const float* left  = (const float*)d_in[1];
    const float* bulk  = (const float*)d_in[2];
    const float* right = (const float*)d_in[3];
    float*       out   = (float*)d_out;

    prep_kernel<<<NSETS, 256>>>(bulk);
    mps_mma_kernel<<<NCTA, TPB>>>(conf, left, right, out);
}